// round 10
// baseline (speedup 1.0000x reference)
#include <cuda_runtime.h>
#include <math.h>

#define NN   50000
#define NE   800000
#define DIM  128
#define HID  128
#define ODIM 64
#define NL   3
#define NPB  8    // nodes per block (final kernel)
#define NPC  16   // nodes per block (input/combine kernels; 50000 % 16 == 0)

// Scratch (no allocation allowed)
__device__ float g_h[(size_t)NN * HID];
__device__ float g_agg[(size_t)NN * HID];
__device__ float g_cnt[NN];

__device__ __forceinline__ float gelu_f(float x) {
    return 0.5f * x * (1.0f + erff(x * 0.70710678118654752440f));
}

// ---------------------------------------------------------------------------
// In-degree count: one thread per edge
// ---------------------------------------------------------------------------
__global__ __launch_bounds__(256) void count_kernel(const int* __restrict__ dst) {
    int e = blockIdx.x * blockDim.x + threadIdx.x;
    if (e < NE) atomicAdd(&g_cnt[dst[e]], 1.0f);
}

// ---------------------------------------------------------------------------
// Fused: layernorm(x) -> @ in_proj + b -> gelu -> g_h
// NPC=16 rows/block, 128 threads; thread -> 4 cols x 4 rows, k-step 2
// (low register pressure). Output written directly, coalesced.
// ---------------------------------------------------------------------------
__global__ __launch_bounds__(128) void input_kernel(
    const float* __restrict__ x,
    const float* __restrict__ lng, const float* __restrict__ lnb,
    const float* __restrict__ W,   const float* __restrict__ pb)
{
    __shared__ __align__(16) float sm[NPC][DIM];
    int nb = blockIdx.x * NPC;
    int tid = threadIdx.x, w = tid >> 5, lane = tid & 31;

    // Phase 1: LN, 4 rows per warp (NN % NPC == 0 -> no bounds checks)
#pragma unroll
    for (int rr = 0; rr < 4; rr++) {
        int r = w + rr * 4;
        int node = nb + r;
        int c = lane * 4;
        float4 v = *(const float4*)(x + (size_t)node * DIM + c);
        float s  = v.x + v.y + v.z + v.w;
        float sq = v.x*v.x + v.y*v.y + v.z*v.z + v.w*v.w;
#pragma unroll
        for (int o = 16; o > 0; o >>= 1) {
            s  += __shfl_xor_sync(0xffffffffu, s,  o);
            sq += __shfl_xor_sync(0xffffffffu, sq, o);
        }
        float m    = s * (1.0f / DIM);
        float rstd = rsqrtf(sq * (1.0f / DIM) - m * m + 1e-5f);
        float4 o4;
        o4.x = (v.x - m) * rstd * lng[c + 0] + lnb[c + 0];
        o4.y = (v.y - m) * rstd * lng[c + 1] + lnb[c + 1];
        o4.z = (v.z - m) * rstd * lng[c + 2] + lnb[c + 2];
        o4.w = (v.w - m) * rstd * lng[c + 3] + lnb[c + 3];
        *(float4*)&sm[r][c] = o4;
    }
    __syncthreads();

    // Phase 2: matvec, 4 cols x 4 rows per thread, k-step 2
    int cp    = (tid & 31) * 4;
    int rbase = (tid >> 5) * 4;

    float acc[4][4];
#pragma unroll
    for (int r = 0; r < 4; r++)
#pragma unroll
        for (int cc = 0; cc < 4; cc++) acc[r][cc] = 0.f;

#pragma unroll 4
    for (int k = 0; k < DIM; k += 2) {
        float4 w0 = *(const float4*)(W + (size_t)(k + 0) * HID + cp);
        float4 w1 = *(const float4*)(W + (size_t)(k + 1) * HID + cp);
#pragma unroll
        for (int r = 0; r < 4; r++) {
            float2 hv = *(const float2*)&sm[rbase + r][k];
            acc[r][0] += hv.x * w0.x + hv.y * w1.x;
            acc[r][1] += hv.x * w0.y + hv.y * w1.y;
            acc[r][2] += hv.x * w0.z + hv.y * w1.z;
            acc[r][3] += hv.x * w0.w + hv.y * w1.w;
        }
    }

    float4 bb = *(const float4*)(pb + cp);
#pragma unroll
    for (int r = 0; r < 4; r++) {
        int node = nb + rbase + r;
        float4 o4;
        o4.x = gelu_f(acc[r][0] + bb.x);
        o4.y = gelu_f(acc[r][1] + bb.y);
        o4.z = gelu_f(acc[r][2] + bb.z);
        o4.w = gelu_f(acc[r][3] + bb.w);
        *(float4*)(g_h + (size_t)node * HID + cp) = o4;
    }
}

// ---------------------------------------------------------------------------
// Scatter-add: warp per edge, vector red.global.add.v4.f32 (R1-proven)
// ---------------------------------------------------------------------------
__global__ __launch_bounds__(256) void scatter_kernel(
    const int* __restrict__ src, const int* __restrict__ dst)
{
    int idx = blockIdx.x * blockDim.x + threadIdx.x;
    int e = idx >> 5;
    if (e >= NE) return;
    int c = (idx & 31) * 4;
    int s = __ldg(src + e);
    int d = __ldg(dst + e);
    float4 v = *(const float4*)(g_h + (size_t)s * HID + c);
    float* p = g_agg + (size_t)d * HID + c;
    asm volatile("red.global.add.v4.f32 [%0], {%1, %2, %3, %4};"
                 :: "l"(p), "f"(v.x), "f"(v.y), "f"(v.z), "f"(v.w)
                 : "memory");
}

// ---------------------------------------------------------------------------
// Fused SAGE tail: mean@Wl + bl + h@Wr -> LN -> gelu -> +h -> g_h
// NPC=16 rows/block. Phase 2: 4 cols x 4 rows per thread, k-step 2 to keep
// only 4 weight float4s live (regs ~55 vs 82 in R9 -> occupancy back up).
// ---------------------------------------------------------------------------
__global__ __launch_bounds__(128) void combine_kernel(
    const float* __restrict__ Wl, const float* __restrict__ bl,
    const float* __restrict__ Wr,
    const float* __restrict__ ng, const float* __restrict__ nbeta)
{
    __shared__ __align__(16) float sm_m[NPC][DIM];
    __shared__ __align__(16) float sm_r[NPC][DIM];
    int nb = blockIdx.x * NPC;
    int tid = threadIdx.x, w = tid >> 5, lane = tid & 31;

    // Phase 1: mean = agg/max(cnt,1), root = h -> smem (4 rows per warp)
#pragma unroll
    for (int rr = 0; rr < 4; rr++) {
        int r = w + rr * 4;
        int node = nb + r;
        int c = lane * 4;
        float inv = 1.0f / fmaxf(g_cnt[node], 1.0f);
        float4 a = *(const float4*)(g_agg + (size_t)node * HID + c);
        float4 h = *(const float4*)(g_h   + (size_t)node * HID + c);
        a.x *= inv; a.y *= inv; a.z *= inv; a.w *= inv;
        *(float4*)&sm_m[r][c] = a;
        *(float4*)&sm_r[r][c] = h;
    }
    __syncthreads();

    // Phase 2: dual matvec; thread -> 4 cols x 4 rows, k-step 2
    int cp    = (tid & 31) * 4;
    int rbase = (tid >> 5) * 4;

    float acc[4][4];
#pragma unroll
    for (int r = 0; r < 4; r++)
#pragma unroll
        for (int cc = 0; cc < 4; cc++) acc[r][cc] = 0.f;

#pragma unroll 4
    for (int k = 0; k < DIM; k += 2) {
        float4 wl0 = *(const float4*)(Wl + (size_t)(k + 0) * HID + cp);
        float4 wl1 = *(const float4*)(Wl + (size_t)(k + 1) * HID + cp);
        float4 wr0 = *(const float4*)(Wr + (size_t)(k + 0) * HID + cp);
        float4 wr1 = *(const float4*)(Wr + (size_t)(k + 1) * HID + cp);
#pragma unroll
        for (int r = 0; r < 4; r++) {
            float2 mv = *(const float2*)&sm_m[rbase + r][k];
            float2 hv = *(const float2*)&sm_r[rbase + r][k];
            acc[r][0] += mv.x * wl0.x + mv.y * wl1.x + hv.x * wr0.x + hv.y * wr1.x;
            acc[r][1] += mv.x * wl0.y + mv.y * wl1.y + hv.x * wr0.y + hv.y * wr1.y;
            acc[r][2] += mv.x * wl0.z + mv.y * wl1.z + hv.x * wr0.z + hv.y * wr1.z;
            acc[r][3] += mv.x * wl0.w + mv.y * wl1.w + hv.x * wr0.w + hv.y * wr1.w;
        }
    }
    __syncthreads();   // all reads of sm_m done before overwrite

    float4 bb = *(const float4*)(bl + cp);
#pragma unroll
    for (int r = 0; r < 4; r++) {
        float4 o4;
        o4.x = acc[r][0] + bb.x;
        o4.y = acc[r][1] + bb.y;
        o4.z = acc[r][2] + bb.z;
        o4.w = acc[r][3] + bb.w;
        *(float4*)&sm_m[rbase + r][cp] = o4;
    }
    __syncthreads();

    // Phase 3: per-row LN + gelu + residual, write back to g_h (4 rows/warp)
#pragma unroll
    for (int rr = 0; rr < 4; rr++) {
        int r = w + rr * 4;
        int node = nb + r;
        int c = lane * 4;
        float4 v = *(const float4*)&sm_m[r][c];
        float s  = v.x + v.y + v.z + v.w;
        float sq = v.x*v.x + v.y*v.y + v.z*v.z + v.w*v.w;
#pragma unroll
        for (int o = 16; o > 0; o >>= 1) {
            s  += __shfl_xor_sync(0xffffffffu, s,  o);
            sq += __shfl_xor_sync(0xffffffffu, sq, o);
        }
        float m    = s * (1.0f / HID);
        float rstd = rsqrtf(sq * (1.0f / HID) - m * m + 1e-5f);
        float4 hres = *(const float4*)&sm_r[r][c];
        float4 o4;
        o4.x = gelu_f((v.x - m) * rstd * ng[c + 0] + nbeta[c + 0]) + hres.x;
        o4.y = gelu_f((v.y - m) * rstd * ng[c + 1] + nbeta[c + 1]) + hres.y;
        o4.z = gelu_f((v.z - m) * rstd * ng[c + 2] + nbeta[c + 2]) + hres.z;
        o4.w = gelu_f((v.w - m) * rstd * ng[c + 3] + nbeta[c + 3]) + hres.w;
        *(float4*)(g_h + (size_t)node * HID + c) = o4;
    }
}

// ---------------------------------------------------------------------------
// Fused: layernorm(h) @ out_proj + b -> out.  (identical to R1-proven version)
// ---------------------------------------------------------------------------
__global__ __launch_bounds__(128) void final_kernel(
    const float* __restrict__ lng, const float* __restrict__ lnb,
    const float* __restrict__ W,   const float* __restrict__ pb,
    float* __restrict__ out)
{
    __shared__ __align__(16) float sm[NPB][DIM];
    int nb = blockIdx.x * NPB;
    int tid = threadIdx.x, w = tid >> 5, lane = tid & 31;

#pragma unroll
    for (int rr = 0; rr < 2; rr++) {
        int r = w + rr * 4;
        int node = nb + r;
        int c = lane * 4;
        float4 v = make_float4(0.f, 0.f, 0.f, 0.f);
        if (node < NN) v = *(const float4*)(g_h + (size_t)node * HID + c);
        float s  = v.x + v.y + v.z + v.w;
        float sq = v.x*v.x + v.y*v.y + v.z*v.z + v.w*v.w;
#pragma unroll
        for (int o = 16; o > 0; o >>= 1) {
            s  += __shfl_xor_sync(0xffffffffu, s,  o);
            sq += __shfl_xor_sync(0xffffffffu, sq, o);
        }
        float m    = s * (1.0f / HID);
        float rstd = rsqrtf(sq * (1.0f / HID) - m * m + 1e-5f);
        float4 o4;
        o4.x = (v.x - m) * rstd * lng[c + 0] + lnb[c + 0];
        o4.y = (v.y - m) * rstd * lng[c + 1] + lnb[c + 1];
        o4.z = (v.z - m) * rstd * lng[c + 2] + lnb[c + 2];
        o4.w = (v.w - m) * rstd * lng[c + 3] + lnb[c + 3];
        *(float4*)&sm[r][c] = o4;
    }
    __syncthreads();

    int jj   = tid & 63;
    int half = tid >> 6;  // 0: rows 0-3, 1: rows 4-7
    float bias = pb[jj];
    float acc[4];
#pragma unroll
    for (int r = 0; r < 4; r++) acc[r] = bias;

#pragma unroll 4
    for (int k = 0; k < HID; k += 4) {
        float w0 = W[(k + 0) * ODIM + jj];
        float w1 = W[(k + 1) * ODIM + jj];
        float w2 = W[(k + 2) * ODIM + jj];
        float w3 = W[(k + 3) * ODIM + jj];
#pragma unroll
        for (int r = 0; r < 4; r++) {
            float4 hv = *(const float4*)&sm[half * 4 + r][k];
            acc[r] += hv.x * w0 + hv.y * w1 + hv.z * w2 + hv.w * w3;
        }
    }
#pragma unroll
    for (int r = 0; r < 4; r++) {
        int node = nb + half * 4 + r;
        if (node < NN) out[(size_t)node * ODIM + jj] = acc[r];
    }
}

// ---------------------------------------------------------------------------
extern "C" void kernel_launch(void* const* d_in, const int* in_sizes, int n_in,
                              void* d_out, int out_size)
{
    const float* x     = (const float*)d_in[0];
    const int*   ei    = (const int*)  d_in[1];
    const float* in_g  = (const float*)d_in[2];
    const float* in_b  = (const float*)d_in[3];
    const float* inW   = (const float*)d_in[4];
    const float* inPb  = (const float*)d_in[5];
    const float* Wl    = (const float*)d_in[6];
    const float* bl    = (const float*)d_in[7];
    const float* Wr    = (const float*)d_in[8];
    const float* ng    = (const float*)d_in[9];
    const float* nbta  = (const float*)d_in[10];
    const float* og    = (const float*)d_in[11];
    const float* ob    = (const float*)d_in[12];
    const float* oW    = (const float*)d_in[13];
    const float* oPb   = (const float*)d_in[14];
    float* out = (float*)d_out;

    const int* src = ei;
    const int* dst = ei + NE;

    void* cntp = nullptr;
    void* aggp = nullptr;
    cudaGetSymbolAddress(&cntp, g_cnt);
    cudaGetSymbolAddress(&aggp, g_agg);

    const int nblk  = (NN + NPB - 1) / NPB;          // 6250 (final)
    const int nblkc = NN / NPC;                      // 3125 (input/combine)
    const int sblk  = (NE * 32 + 255) / 256;         // 100000

    cudaMemsetAsync(cntp, 0, NN * sizeof(float));
    count_kernel<<<(NE + 255) / 256, 256>>>(dst);
    input_kernel<<<nblkc, 128>>>(x, in_g, in_b, inW, inPb);

    for (int l = 0; l < NL; l++) {
        cudaMemsetAsync(aggp, 0, (size_t)NN * HID * sizeof(float));
        scatter_kernel<<<sblk, 256>>>(src, dst);
        combine_kernel<<<nblkc, 128>>>(Wl + (size_t)l * HID * HID,
                                       bl + l * HID,
                                       Wr + (size_t)l * HID * HID,
                                       ng + l * HID,
                                       nbta + l * HID);
    }

    final_kernel<<<nblk, 128>>>(og, ob, oW, oPb, out);
}

// round 11
// speedup vs baseline: 1.2121x; 1.2121x over previous
#include <cuda_runtime.h>
#include <math.h>

#define NN   50000
#define NE   800000
#define DIM  128
#define HID  128
#define ODIM 64
#define NL   3
#define NPB  8    // nodes per block (input/final kernels)
#define NPC  16   // nodes per block (combine kernel; 50000 % 16 == 0)
#define SCAN_T 1024

// Scratch (no allocation allowed)
__device__ float g_h[(size_t)NN * HID];
__device__ float g_agg[(size_t)NN * HID];
__device__ int   g_deg[NN];
__device__ int   g_off[NN + 1];
__device__ int   g_cur[NN];
__device__ int   g_esrc[NE];

__device__ __forceinline__ float gelu_f(float x) {
    return 0.5f * x * (1.0f + erff(x * 0.70710678118654752440f));
}

// ---------------------------------------------------------------------------
// In-degree count (int): one thread per edge
// ---------------------------------------------------------------------------
__global__ __launch_bounds__(256) void count_kernel(const int* __restrict__ dst) {
    int e = blockIdx.x * blockDim.x + threadIdx.x;
    if (e < NE) atomicAdd(&g_deg[dst[e]], 1);
}

// ---------------------------------------------------------------------------
// Exclusive prefix sum of g_deg -> g_off (and g_cur copy). One block.
// ---------------------------------------------------------------------------
__global__ __launch_bounds__(SCAN_T) void scan_kernel() {
    __shared__ int ssum[SCAN_T];
    int tid = threadIdx.x;
    const int CH = (NN + SCAN_T - 1) / SCAN_T;   // 49
    int base = tid * CH;

    int s = 0;
    for (int i = 0; i < CH; i++) {
        int idx = base + i;
        if (idx < NN) s += g_deg[idx];
    }
    ssum[tid] = s;
    __syncthreads();

    // Hillis-Steele inclusive scan over the 1024 partial sums
    for (int off = 1; off < SCAN_T; off <<= 1) {
        int v = 0;
        if (tid >= off) v = ssum[tid - off];
        __syncthreads();
        if (tid >= off) ssum[tid] += v;
        __syncthreads();
    }

    int run = (tid == 0) ? 0 : ssum[tid - 1];   // exclusive base for this chunk
    for (int i = 0; i < CH; i++) {
        int idx = base + i;
        if (idx < NN) {
            g_off[idx] = run;
            g_cur[idx] = run;
            run += g_deg[idx];
        }
    }
    if (tid == SCAN_T - 1) g_off[NN] = run;
}

// ---------------------------------------------------------------------------
// Bucket-fill: g_esrc[pos] = src[e], grouped by dst
// ---------------------------------------------------------------------------
__global__ __launch_bounds__(256) void fill_kernel(
    const int* __restrict__ src, const int* __restrict__ dst)
{
    int e = blockIdx.x * blockDim.x + threadIdx.x;
    if (e >= NE) return;
    int d = dst[e];
    int pos = atomicAdd(&g_cur[d], 1);
    g_esrc[pos] = src[e];
}

// ---------------------------------------------------------------------------
// CSR aggregate: warp per node; accumulate neighbor rows, write MEAN.
// No atomics, no memset. Unroll-2 for MLP.
// ---------------------------------------------------------------------------
__global__ __launch_bounds__(256) void aggregate_kernel() {
    int gw = (blockIdx.x * blockDim.x + threadIdx.x) >> 5;
    if (gw >= NN) return;
    int lane = threadIdx.x & 31;
    int c = lane * 4;

    int beg = __ldg(&g_off[gw]);
    int end = __ldg(&g_off[gw + 1]);

    float4 a0 = make_float4(0.f, 0.f, 0.f, 0.f);
    float4 a1 = make_float4(0.f, 0.f, 0.f, 0.f);
    int i = beg;
    for (; i + 2 <= end; i += 2) {
        int s0 = __ldg(&g_esrc[i]);
        int s1 = __ldg(&g_esrc[i + 1]);
        float4 v0 = *(const float4*)(g_h + (size_t)s0 * HID + c);
        float4 v1 = *(const float4*)(g_h + (size_t)s1 * HID + c);
        a0.x += v0.x; a0.y += v0.y; a0.z += v0.z; a0.w += v0.w;
        a1.x += v1.x; a1.y += v1.y; a1.z += v1.z; a1.w += v1.w;
    }
    if (i < end) {
        int s0 = __ldg(&g_esrc[i]);
        float4 v0 = *(const float4*)(g_h + (size_t)s0 * HID + c);
        a0.x += v0.x; a0.y += v0.y; a0.z += v0.z; a0.w += v0.w;
    }
    int deg = end - beg;
    float inv = 1.0f / (float)max(deg, 1);
    float4 m;
    m.x = (a0.x + a1.x) * inv;
    m.y = (a0.y + a1.y) * inv;
    m.z = (a0.z + a1.z) * inv;
    m.w = (a0.w + a1.w) * inv;
    *(float4*)(g_agg + (size_t)gw * HID + c) = m;
}

// ---------------------------------------------------------------------------
// Fused: layernorm(x) -> @ in_proj + b -> gelu -> g_h  (R9-proven)
// ---------------------------------------------------------------------------
__global__ __launch_bounds__(128) void input_kernel(
    const float* __restrict__ x,
    const float* __restrict__ lng, const float* __restrict__ lnb,
    const float* __restrict__ W,   const float* __restrict__ pb)
{
    __shared__ __align__(16) float sm[NPB][DIM];
    int nb = blockIdx.x * NPB;
    int tid = threadIdx.x, w = tid >> 5, lane = tid & 31;

#pragma unroll
    for (int rr = 0; rr < 2; rr++) {
        int r = w + rr * 4;
        int node = nb + r;
        int c = lane * 4;
        float4 v = make_float4(0.f, 0.f, 0.f, 0.f);
        if (node < NN) v = *(const float4*)(x + (size_t)node * DIM + c);
        float s  = v.x + v.y + v.z + v.w;
        float sq = v.x*v.x + v.y*v.y + v.z*v.z + v.w*v.w;
#pragma unroll
        for (int o = 16; o > 0; o >>= 1) {
            s  += __shfl_xor_sync(0xffffffffu, s,  o);
            sq += __shfl_xor_sync(0xffffffffu, sq, o);
        }
        float m    = s * (1.0f / DIM);
        float rstd = rsqrtf(sq * (1.0f / DIM) - m * m + 1e-5f);
        float4 o4;
        o4.x = (v.x - m) * rstd * lng[c + 0] + lnb[c + 0];
        o4.y = (v.y - m) * rstd * lng[c + 1] + lnb[c + 1];
        o4.z = (v.z - m) * rstd * lng[c + 2] + lnb[c + 2];
        o4.w = (v.w - m) * rstd * lng[c + 3] + lnb[c + 3];
        *(float4*)&sm[r][c] = o4;
    }
    __syncthreads();

    int j = tid;
    float bias = pb[j];
    float acc[NPB];
#pragma unroll
    for (int r = 0; r < NPB; r++) acc[r] = bias;

#pragma unroll 4
    for (int k = 0; k < DIM; k += 4) {
        float w0 = W[(k + 0) * HID + j];
        float w1 = W[(k + 1) * HID + j];
        float w2 = W[(k + 2) * HID + j];
        float w3 = W[(k + 3) * HID + j];
#pragma unroll
        for (int r = 0; r < NPB; r++) {
            float4 hv = *(const float4*)&sm[r][k];
            acc[r] += hv.x * w0 + hv.y * w1 + hv.z * w2 + hv.w * w3;
        }
    }
#pragma unroll
    for (int r = 0; r < NPB; r++) {
        int node = nb + r;
        if (node < NN) g_h[(size_t)node * HID + j] = gelu_f(acc[r]);
    }
}

// ---------------------------------------------------------------------------
// Fused SAGE tail: mean@Wl + bl + h@Wr -> LN -> gelu -> +h -> g_h
// (R9-proven 4col x 4row tile; phase 1 now loads mean directly from g_agg)
// ---------------------------------------------------------------------------
__global__ __launch_bounds__(128) void combine_kernel(
    const float* __restrict__ Wl, const float* __restrict__ bl,
    const float* __restrict__ Wr,
    const float* __restrict__ ng, const float* __restrict__ nbeta)
{
    __shared__ __align__(16) float sm_m[NPC][DIM];
    __shared__ __align__(16) float sm_r[NPC][DIM];
    int nb = blockIdx.x * NPC;
    int tid = threadIdx.x, w = tid >> 5, lane = tid & 31;

    // Phase 1: mean (precomputed) and root rows -> smem (4 rows per warp)
#pragma unroll
    for (int rr = 0; rr < 4; rr++) {
        int r = w + rr * 4;
        int node = nb + r;
        int c = lane * 4;
        float4 a = *(const float4*)(g_agg + (size_t)node * HID + c);
        float4 h = *(const float4*)(g_h   + (size_t)node * HID + c);
        *(float4*)&sm_m[r][c] = a;
        *(float4*)&sm_r[r][c] = h;
    }
    __syncthreads();

    // Phase 2: dual matvec; thread -> 4 cols (cp..cp+3) x 4 rows (rbase..+3)
    int cp    = (tid & 31) * 4;
    int rbase = (tid >> 5) * 4;

    float acc[4][4];
#pragma unroll
    for (int r = 0; r < 4; r++)
#pragma unroll
        for (int cc = 0; cc < 4; cc++) acc[r][cc] = 0.f;

#pragma unroll 4
    for (int k = 0; k < DIM; k += 4) {
        float4 wl0 = *(const float4*)(Wl + (size_t)(k + 0) * HID + cp);
        float4 wl1 = *(const float4*)(Wl + (size_t)(k + 1) * HID + cp);
        float4 wl2 = *(const float4*)(Wl + (size_t)(k + 2) * HID + cp);
        float4 wl3 = *(const float4*)(Wl + (size_t)(k + 3) * HID + cp);
        float4 wr0 = *(const float4*)(Wr + (size_t)(k + 0) * HID + cp);
        float4 wr1 = *(const float4*)(Wr + (size_t)(k + 1) * HID + cp);
        float4 wr2 = *(const float4*)(Wr + (size_t)(k + 2) * HID + cp);
        float4 wr3 = *(const float4*)(Wr + (size_t)(k + 3) * HID + cp);
#pragma unroll
        for (int r = 0; r < 4; r++) {
            float4 mv = *(const float4*)&sm_m[rbase + r][k];
            float4 hv = *(const float4*)&sm_r[rbase + r][k];
            acc[r][0] += mv.x * wl0.x + mv.y * wl1.x + mv.z * wl2.x + mv.w * wl3.x
                       + hv.x * wr0.x + hv.y * wr1.x + hv.z * wr2.x + hv.w * wr3.x;
            acc[r][1] += mv.x * wl0.y + mv.y * wl1.y + mv.z * wl2.y + mv.w * wl3.y
                       + hv.x * wr0.y + hv.y * wr1.y + hv.z * wr2.y + hv.w * wr3.y;
            acc[r][2] += mv.x * wl0.z + mv.y * wl1.z + mv.z * wl2.z + mv.w * wl3.z
                       + hv.x * wr0.z + hv.y * wr1.z + hv.z * wr2.z + hv.w * wr3.z;
            acc[r][3] += mv.x * wl0.w + mv.y * wl1.w + mv.z * wl2.w + mv.w * wl3.w
                       + hv.x * wr0.w + hv.y * wr1.w + hv.z * wr2.w + hv.w * wr3.w;
        }
    }
    __syncthreads();   // all reads of sm_m done before overwrite

    float4 bb = *(const float4*)(bl + cp);
#pragma unroll
    for (int r = 0; r < 4; r++) {
        float4 o4;
        o4.x = acc[r][0] + bb.x;
        o4.y = acc[r][1] + bb.y;
        o4.z = acc[r][2] + bb.z;
        o4.w = acc[r][3] + bb.w;
        *(float4*)&sm_m[rbase + r][cp] = o4;
    }
    __syncthreads();

    // Phase 3: per-row LN + gelu + residual, write back to g_h (4 rows/warp)
#pragma unroll
    for (int rr = 0; rr < 4; rr++) {
        int r = w + rr * 4;
        int node = nb + r;
        int c = lane * 4;
        float4 v = *(const float4*)&sm_m[r][c];
        float s  = v.x + v.y + v.z + v.w;
        float sq = v.x*v.x + v.y*v.y + v.z*v.z + v.w*v.w;
#pragma unroll
        for (int o = 16; o > 0; o >>= 1) {
            s  += __shfl_xor_sync(0xffffffffu, s,  o);
            sq += __shfl_xor_sync(0xffffffffu, sq, o);
        }
        float m    = s * (1.0f / HID);
        float rstd = rsqrtf(sq * (1.0f / HID) - m * m + 1e-5f);
        float4 hres = *(const float4*)&sm_r[r][c];
        float4 o4;
        o4.x = gelu_f((v.x - m) * rstd * ng[c + 0] + nbeta[c + 0]) + hres.x;
        o4.y = gelu_f((v.y - m) * rstd * ng[c + 1] + nbeta[c + 1]) + hres.y;
        o4.z = gelu_f((v.z - m) * rstd * ng[c + 2] + nbeta[c + 2]) + hres.z;
        o4.w = gelu_f((v.w - m) * rstd * ng[c + 3] + nbeta[c + 3]) + hres.w;
        *(float4*)(g_h + (size_t)node * HID + c) = o4;
    }
}

// ---------------------------------------------------------------------------
// Fused: layernorm(h) @ out_proj + b -> out.  (R9-proven)
// ---------------------------------------------------------------------------
__global__ __launch_bounds__(128) void final_kernel(
    const float* __restrict__ lng, const float* __restrict__ lnb,
    const float* __restrict__ W,   const float* __restrict__ pb,
    float* __restrict__ out)
{
    __shared__ __align__(16) float sm[NPB][DIM];
    int nb = blockIdx.x * NPB;
    int tid = threadIdx.x, w = tid >> 5, lane = tid & 31;

#pragma unroll
    for (int rr = 0; rr < 2; rr++) {
        int r = w + rr * 4;
        int node = nb + r;
        int c = lane * 4;
        float4 v = make_float4(0.f, 0.f, 0.f, 0.f);
        if (node < NN) v = *(const float4*)(g_h + (size_t)node * HID + c);
        float s  = v.x + v.y + v.z + v.w;
        float sq = v.x*v.x + v.y*v.y + v.z*v.z + v.w*v.w;
#pragma unroll
        for (int o = 16; o > 0; o >>= 1) {
            s  += __shfl_xor_sync(0xffffffffu, s,  o);
            sq += __shfl_xor_sync(0xffffffffu, sq, o);
        }
        float m    = s * (1.0f / HID);
        float rstd = rsqrtf(sq * (1.0f / HID) - m * m + 1e-5f);
        float4 o4;
        o4.x = (v.x - m) * rstd * lng[c + 0] + lnb[c + 0];
        o4.y = (v.y - m) * rstd * lng[c + 1] + lnb[c + 1];
        o4.z = (v.z - m) * rstd * lng[c + 2] + lnb[c + 2];
        o4.w = (v.w - m) * rstd * lng[c + 3] + lnb[c + 3];
        *(float4*)&sm[r][c] = o4;
    }
    __syncthreads();

    int jj   = tid & 63;
    int half = tid >> 6;  // 0: rows 0-3, 1: rows 4-7
    float bias = pb[jj];
    float acc[4];
#pragma unroll
    for (int r = 0; r < 4; r++) acc[r] = bias;

#pragma unroll 4
    for (int k = 0; k < HID; k += 4) {
        float w0 = W[(k + 0) * ODIM + jj];
        float w1 = W[(k + 1) * ODIM + jj];
        float w2 = W[(k + 2) * ODIM + jj];
        float w3 = W[(k + 3) * ODIM + jj];
#pragma unroll
        for (int r = 0; r < 4; r++) {
            float4 hv = *(const float4*)&sm[half * 4 + r][k];
            acc[r] += hv.x * w0 + hv.y * w1 + hv.z * w2 + hv.w * w3;
        }
    }
#pragma unroll
    for (int r = 0; r < 4; r++) {
        int node = nb + half * 4 + r;
        if (node < NN) out[(size_t)node * ODIM + jj] = acc[r];
    }
}

// ---------------------------------------------------------------------------
extern "C" void kernel_launch(void* const* d_in, const int* in_sizes, int n_in,
                              void* d_out, int out_size)
{
    const float* x     = (const float*)d_in[0];
    const int*   ei    = (const int*)  d_in[1];
    const float* in_g  = (const float*)d_in[2];
    const float* in_b  = (const float*)d_in[3];
    const float* inW   = (const float*)d_in[4];
    const float* inPb  = (const float*)d_in[5];
    const float* Wl    = (const float*)d_in[6];
    const float* bl    = (const float*)d_in[7];
    const float* Wr    = (const float*)d_in[8];
    const float* ng    = (const float*)d_in[9];
    const float* nbta  = (const float*)d_in[10];
    const float* og    = (const float*)d_in[11];
    const float* ob    = (const float*)d_in[12];
    const float* oW    = (const float*)d_in[13];
    const float* oPb   = (const float*)d_in[14];
    float* out = (float*)d_out;

    const int* src = ei;
    const int* dst = ei + NE;

    void* degp = nullptr;
    cudaGetSymbolAddress(&degp, g_deg);

    const int nblk  = (NN + NPB - 1) / NPB;          // 6250 (input/final)
    const int nblkc = NN / NPC;                      // 3125 (combine)
    const int ablk  = (NN * 32 + 255) / 256;         // 6250 (aggregate)

    // CSR build (per launch; graph-captured)
    cudaMemsetAsync(degp, 0, NN * sizeof(int));
    count_kernel<<<(NE + 255) / 256, 256>>>(dst);
    scan_kernel<<<1, SCAN_T>>>();
    fill_kernel<<<(NE + 255) / 256, 256>>>(src, dst);

    input_kernel<<<nblk, 128>>>(x, in_g, in_b, inW, inPb);

    for (int l = 0; l < NL; l++) {
        aggregate_kernel<<<ablk, 256>>>();
        combine_kernel<<<nblkc, 128>>>(Wl + (size_t)l * HID * HID,
                                       bl + l * HID,
                                       Wr + (size_t)l * HID * HID,
                                       ng + l * HID,
                                       nbta + l * HID);
    }

    final_kernel<<<nblk, 128>>>(og, ob, oW, oPb, out);
}

// round 13
// speedup vs baseline: 1.3036x; 1.0755x over previous
#include <cuda_runtime.h>
#include <math.h>

#define NN   50000
#define NE   800000
#define DIM  128
#define HID  128
#define ODIM 64
#define NL   3
#define NPB  8    // nodes per block (final kernel)
#define NPC  16   // nodes per block (input/combine; 50000 % 16 == 0)
#define SCAN_T 1024

// Scratch (no allocation allowed). Ping-pong feature buffers.
__device__ float g_h0[(size_t)NN * HID];
__device__ float g_h1[(size_t)NN * HID];
__device__ int   g_deg[NN];
__device__ int   g_off[NN + 1];
__device__ int   g_cur[NN];
__device__ int   g_esrc[NE];

__device__ __forceinline__ float gelu_f(float x) {
    return 0.5f * x * (1.0f + erff(x * 0.70710678118654752440f));
}

// ---------------------------------------------------------------------------
// In-degree count (int): one thread per edge
// ---------------------------------------------------------------------------
__global__ __launch_bounds__(256) void count_kernel(const int* __restrict__ dst) {
    int e = blockIdx.x * blockDim.x + threadIdx.x;
    if (e < NE) atomicAdd(&g_deg[dst[e]], 1);
}

// ---------------------------------------------------------------------------
// Exclusive prefix sum of g_deg -> g_off (and g_cur copy). One block.
// ---------------------------------------------------------------------------
__global__ __launch_bounds__(SCAN_T) void scan_kernel() {
    __shared__ int ssum[SCAN_T];
    int tid = threadIdx.x;
    const int CH = (NN + SCAN_T - 1) / SCAN_T;   // 49
    int base = tid * CH;

    int s = 0;
    for (int i = 0; i < CH; i++) {
        int idx = base + i;
        if (idx < NN) s += g_deg[idx];
    }
    ssum[tid] = s;
    __syncthreads();

    for (int off = 1; off < SCAN_T; off <<= 1) {
        int v = 0;
        if (tid >= off) v = ssum[tid - off];
        __syncthreads();
        if (tid >= off) ssum[tid] += v;
        __syncthreads();
    }

    int run = (tid == 0) ? 0 : ssum[tid - 1];
    for (int i = 0; i < CH; i++) {
        int idx = base + i;
        if (idx < NN) {
            g_off[idx] = run;
            g_cur[idx] = run;
            run += g_deg[idx];
        }
    }
    if (tid == SCAN_T - 1) g_off[NN] = run;
}

// ---------------------------------------------------------------------------
// Bucket-fill: g_esrc[pos] = src[e], grouped by dst
// ---------------------------------------------------------------------------
__global__ __launch_bounds__(256) void fill_kernel(
    const int* __restrict__ src, const int* __restrict__ dst)
{
    int e = blockIdx.x * blockDim.x + threadIdx.x;
    if (e >= NE) return;
    int d = dst[e];
    int pos = atomicAdd(&g_cur[d], 1);
    g_esrc[pos] = src[e];
}

// ---------------------------------------------------------------------------
// Fused: layernorm(x) -> @ in_proj + b -> gelu -> hout
// NPC=16 rows/block; phase 2 uses the R9-validated 4col x 4row tile.
// ---------------------------------------------------------------------------
__global__ __launch_bounds__(128) void input_kernel(
    const float* __restrict__ x,
    const float* __restrict__ lng, const float* __restrict__ lnb,
    const float* __restrict__ W,   const float* __restrict__ pb,
    float* __restrict__ hout)
{
    __shared__ __align__(16) float sm[NPC][DIM];
    int nb = blockIdx.x * NPC;
    int tid = threadIdx.x, w = tid >> 5, lane = tid & 31;

    // Phase 1: LN, 4 rows per warp (NN % NPC == 0 -> no bounds checks)
#pragma unroll
    for (int rr = 0; rr < 4; rr++) {
        int r = w + rr * 4;
        int node = nb + r;
        int c = lane * 4;
        float4 v = *(const float4*)(x + (size_t)node * DIM + c);
        float s  = v.x + v.y + v.z + v.w;
        float sq = v.x*v.x + v.y*v.y + v.z*v.z + v.w*v.w;
#pragma unroll
        for (int o = 16; o > 0; o >>= 1) {
            s  += __shfl_xor_sync(0xffffffffu, s,  o);
            sq += __shfl_xor_sync(0xffffffffu, sq, o);
        }
        float m    = s * (1.0f / DIM);
        float rstd = rsqrtf(sq * (1.0f / DIM) - m * m + 1e-5f);
        float4 o4;
        o4.x = (v.x - m) * rstd * lng[c + 0] + lnb[c + 0];
        o4.y = (v.y - m) * rstd * lng[c + 1] + lnb[c + 1];
        o4.z = (v.z - m) * rstd * lng[c + 2] + lnb[c + 2];
        o4.w = (v.w - m) * rstd * lng[c + 3] + lnb[c + 3];
        *(float4*)&sm[r][c] = o4;
    }
    __syncthreads();

    // Phase 2: matvec, 4 cols x 4 rows per thread, k-step 4
    int cp    = (tid & 31) * 4;
    int rbase = (tid >> 5) * 4;

    float acc[4][4];
#pragma unroll
    for (int r = 0; r < 4; r++)
#pragma unroll
        for (int cc = 0; cc < 4; cc++) acc[r][cc] = 0.f;

#pragma unroll 4
    for (int k = 0; k < DIM; k += 4) {
        float4 w0 = *(const float4*)(W + (size_t)(k + 0) * HID + cp);
        float4 w1 = *(const float4*)(W + (size_t)(k + 1) * HID + cp);
        float4 w2 = *(const float4*)(W + (size_t)(k + 2) * HID + cp);
        float4 w3 = *(const float4*)(W + (size_t)(k + 3) * HID + cp);
#pragma unroll
        for (int r = 0; r < 4; r++) {
            float4 hv = *(const float4*)&sm[rbase + r][k];
            acc[r][0] += hv.x * w0.x + hv.y * w1.x + hv.z * w2.x + hv.w * w3.x;
            acc[r][1] += hv.x * w0.y + hv.y * w1.y + hv.z * w2.y + hv.w * w3.y;
            acc[r][2] += hv.x * w0.z + hv.y * w1.z + hv.z * w2.z + hv.w * w3.z;
            acc[r][3] += hv.x * w0.w + hv.y * w1.w + hv.z * w2.w + hv.w * w3.w;
        }
    }

    float4 bb = *(const float4*)(pb + cp);
#pragma unroll
    for (int r = 0; r < 4; r++) {
        int node = nb + rbase + r;
        float4 o4;
        o4.x = gelu_f(acc[r][0] + bb.x);
        o4.y = gelu_f(acc[r][1] + bb.y);
        o4.z = gelu_f(acc[r][2] + bb.z);
        o4.w = gelu_f(acc[r][3] + bb.w);
        *(float4*)(hout + (size_t)node * HID + cp) = o4;
    }
}

// ---------------------------------------------------------------------------
// Fused SAGE layer, ping-pong: reads hin ONLY, writes hout ONLY.
// [CSR gather -> mean] + mean@Wl + bl + hin@Wr -> LN -> gelu -> +hin -> hout
// ---------------------------------------------------------------------------
__global__ __launch_bounds__(128) void combine_kernel(
    const float* __restrict__ hin, float* __restrict__ hout,
    const float* __restrict__ Wl,  const float* __restrict__ bl,
    const float* __restrict__ Wr,
    const float* __restrict__ ng,  const float* __restrict__ nbeta)
{
    __shared__ __align__(16) float sm_m[NPC][DIM];
    __shared__ __align__(16) float sm_r[NPC][DIM];
    int nb = blockIdx.x * NPC;
    int tid = threadIdx.x, w = tid >> 5, lane = tid & 31;
    int c = lane * 4;

    // Phase 1: per warp, 4 nodes: CSR gather from hin -> mean; root from hin
#pragma unroll
    for (int rr = 0; rr < 4; rr++) {
        int r = w + rr * 4;
        int node = nb + r;

        int beg = __ldg(&g_off[node]);
        int end = __ldg(&g_off[node + 1]);

        float4 a0 = make_float4(0.f, 0.f, 0.f, 0.f);
        float4 a1 = make_float4(0.f, 0.f, 0.f, 0.f);
        int i = beg;
        for (; i + 2 <= end; i += 2) {
            int s0 = __ldg(&g_esrc[i]);
            int s1 = __ldg(&g_esrc[i + 1]);
            float4 v0 = *(const float4*)(hin + (size_t)s0 * HID + c);
            float4 v1 = *(const float4*)(hin + (size_t)s1 * HID + c);
            a0.x += v0.x; a0.y += v0.y; a0.z += v0.z; a0.w += v0.w;
            a1.x += v1.x; a1.y += v1.y; a1.z += v1.z; a1.w += v1.w;
        }
        if (i < end) {
            int s0 = __ldg(&g_esrc[i]);
            float4 v0 = *(const float4*)(hin + (size_t)s0 * HID + c);
            a0.x += v0.x; a0.y += v0.y; a0.z += v0.z; a0.w += v0.w;
        }
        float inv = 1.0f / (float)max(end - beg, 1);
        float4 m;
        m.x = (a0.x + a1.x) * inv;
        m.y = (a0.y + a1.y) * inv;
        m.z = (a0.z + a1.z) * inv;
        m.w = (a0.w + a1.w) * inv;
        *(float4*)&sm_m[r][c] = m;

        float4 h = *(const float4*)(hin + (size_t)node * HID + c);
        *(float4*)&sm_r[r][c] = h;
    }
    __syncthreads();

    // Phase 2: dual matvec; thread -> 4 cols (cp..cp+3) x 4 rows (rbase..+3)
    int cp    = (tid & 31) * 4;
    int rbase = (tid >> 5) * 4;

    float acc[4][4];
#pragma unroll
    for (int r = 0; r < 4; r++)
#pragma unroll
        for (int cc = 0; cc < 4; cc++) acc[r][cc] = 0.f;

#pragma unroll 4
    for (int k = 0; k < DIM; k += 4) {
        float4 wl0 = *(const float4*)(Wl + (size_t)(k + 0) * HID + cp);
        float4 wl1 = *(const float4*)(Wl + (size_t)(k + 1) * HID + cp);
        float4 wl2 = *(const float4*)(Wl + (size_t)(k + 2) * HID + cp);
        float4 wl3 = *(const float4*)(Wl + (size_t)(k + 3) * HID + cp);
        float4 wr0 = *(const float4*)(Wr + (size_t)(k + 0) * HID + cp);
        float4 wr1 = *(const float4*)(Wr + (size_t)(k + 1) * HID + cp);
        float4 wr2 = *(const float4*)(Wr + (size_t)(k + 2) * HID + cp);
        float4 wr3 = *(const float4*)(Wr + (size_t)(k + 3) * HID + cp);
#pragma unroll
        for (int r = 0; r < 4; r++) {
            float4 mv = *(const float4*)&sm_m[rbase + r][k];
            float4 hv = *(const float4*)&sm_r[rbase + r][k];
            acc[r][0] += mv.x * wl0.x + mv.y * wl1.x + mv.z * wl2.x + mv.w * wl3.x
                       + hv.x * wr0.x + hv.y * wr1.x + hv.z * wr2.x + hv.w * wr3.x;
            acc[r][1] += mv.x * wl0.y + mv.y * wl1.y + mv.z * wl2.y + mv.w * wl3.y
                       + hv.x * wr0.y + hv.y * wr1.y + hv.z * wr2.y + hv.w * wr3.y;
            acc[r][2] += mv.x * wl0.z + mv.y * wl1.z + mv.z * wl2.z + mv.w * wl3.z
                       + hv.x * wr0.z + hv.y * wr1.z + hv.z * wr2.z + hv.w * wr3.z;
            acc[r][3] += mv.x * wl0.w + mv.y * wl1.w + mv.z * wl2.w + mv.w * wl3.w
                       + hv.x * wr0.w + hv.y * wr1.w + hv.z * wr2.w + hv.w * wr3.w;
        }
    }
    __syncthreads();   // all reads of sm_m done before overwrite

    float4 bb = *(const float4*)(bl + cp);
#pragma unroll
    for (int r = 0; r < 4; r++) {
        float4 o4;
        o4.x = acc[r][0] + bb.x;
        o4.y = acc[r][1] + bb.y;
        o4.z = acc[r][2] + bb.z;
        o4.w = acc[r][3] + bb.w;
        *(float4*)&sm_m[rbase + r][cp] = o4;
    }
    __syncthreads();

    // Phase 3: per-row LN + gelu + residual -> hout (4 rows/warp)
#pragma unroll
    for (int rr = 0; rr < 4; rr++) {
        int r = w + rr * 4;
        int node = nb + r;
        float4 v = *(const float4*)&sm_m[r][c];
        float s  = v.x + v.y + v.z + v.w;
        float sq = v.x*v.x + v.y*v.y + v.z*v.z + v.w*v.w;
#pragma unroll
        for (int o = 16; o > 0; o >>= 1) {
            s  += __shfl_xor_sync(0xffffffffu, s,  o);
            sq += __shfl_xor_sync(0xffffffffu, sq, o);
        }
        float m    = s * (1.0f / HID);
        float rstd = rsqrtf(sq * (1.0f / HID) - m * m + 1e-5f);
        float4 hres = *(const float4*)&sm_r[r][c];
        float4 o4;
        o4.x = gelu_f((v.x - m) * rstd * ng[c + 0] + nbeta[c + 0]) + hres.x;
        o4.y = gelu_f((v.y - m) * rstd * ng[c + 1] + nbeta[c + 1]) + hres.y;
        o4.z = gelu_f((v.z - m) * rstd * ng[c + 2] + nbeta[c + 2]) + hres.z;
        o4.w = gelu_f((v.w - m) * rstd * ng[c + 3] + nbeta[c + 3]) + hres.w;
        *(float4*)(hout + (size_t)node * HID + c) = o4;
    }
}

// ---------------------------------------------------------------------------
// Fused: layernorm(hin) @ out_proj + b -> out.  (R9-proven, hin param)
// ---------------------------------------------------------------------------
__global__ __launch_bounds__(128) void final_kernel(
    const float* __restrict__ hin,
    const float* __restrict__ lng, const float* __restrict__ lnb,
    const float* __restrict__ W,   const float* __restrict__ pb,
    float* __restrict__ out)
{
    __shared__ __align__(16) float sm[NPB][DIM];
    int nb = blockIdx.x * NPB;
    int tid = threadIdx.x, w = tid >> 5, lane = tid & 31;

#pragma unroll
    for (int rr = 0; rr < 2; rr++) {
        int r = w + rr * 4;
        int node = nb + r;
        int c = lane * 4;
        float4 v = make_float4(0.f, 0.f, 0.f, 0.f);
        if (node < NN) v = *(const float4*)(hin + (size_t)node * HID + c);
        float s  = v.x + v.y + v.z + v.w;
        float sq = v.x*v.x + v.y*v.y + v.z*v.z + v.w*v.w;
#pragma unroll
        for (int o = 16; o > 0; o >>= 1) {
            s  += __shfl_xor_sync(0xffffffffu, s,  o);
            sq += __shfl_xor_sync(0xffffffffu, sq, o);
        }
        float m    = s * (1.0f / HID);
        float rstd = rsqrtf(sq * (1.0f / HID) - m * m + 1e-5f);
        float4 o4;
        o4.x = (v.x - m) * rstd * lng[c + 0] + lnb[c + 0];
        o4.y = (v.y - m) * rstd * lng[c + 1] + lnb[c + 1];
        o4.z = (v.z - m) * rstd * lng[c + 2] + lnb[c + 2];
        o4.w = (v.w - m) * rstd * lng[c + 3] + lnb[c + 3];
        *(float4*)&sm[r][c] = o4;
    }
    __syncthreads();

    int jj   = tid & 63;
    int half = tid >> 6;  // 0: rows 0-3, 1: rows 4-7
    float bias = pb[jj];
    float acc[4];
#pragma unroll
    for (int r = 0; r < 4; r++) acc[r] = bias;

#pragma unroll 4
    for (int k = 0; k < HID; k += 4) {
        float w0 = W[(k + 0) * ODIM + jj];
        float w1 = W[(k + 1) * ODIM + jj];
        float w2 = W[(k + 2) * ODIM + jj];
        float w3 = W[(k + 3) * ODIM + jj];
#pragma unroll
        for (int r = 0; r < 4; r++) {
            float4 hv = *(const float4*)&sm[half * 4 + r][k];
            acc[r] += hv.x * w0 + hv.y * w1 + hv.z * w2 + hv.w * w3;
        }
    }
#pragma unroll
    for (int r = 0; r < 4; r++) {
        int node = nb + half * 4 + r;
        if (node < NN) out[(size_t)node * ODIM + jj] = acc[r];
    }
}

// ---------------------------------------------------------------------------
extern "C" void kernel_launch(void* const* d_in, const int* in_sizes, int n_in,
                              void* d_out, int out_size)
{
    const float* x     = (const float*)d_in[0];
    const int*   ei    = (const int*)  d_in[1];
    const float* in_g  = (const float*)d_in[2];
    const float* in_b  = (const float*)d_in[3];
    const float* inW   = (const float*)d_in[4];
    const float* inPb  = (const float*)d_in[5];
    const float* Wl    = (const float*)d_in[6];
    const float* bl    = (const float*)d_in[7];
    const float* Wr    = (const float*)d_in[8];
    const float* ng    = (const float*)d_in[9];
    const float* nbta  = (const float*)d_in[10];
    const float* og    = (const float*)d_in[11];
    const float* ob    = (const float*)d_in[12];
    const float* oW    = (const float*)d_in[13];
    const float* oPb   = (const float*)d_in[14];
    float* out = (float*)d_out;

    const int* src = ei;
    const int* dst = ei + NE;

    void* degp = nullptr;
    void* h0p = nullptr;
    void* h1p = nullptr;
    cudaGetSymbolAddress(&degp, g_deg);
    cudaGetSymbolAddress(&h0p, g_h0);
    cudaGetSymbolAddress(&h1p, g_h1);
    float* buf[2] = { (float*)h0p, (float*)h1p };

    const int nblk  = (NN + NPB - 1) / NPB;          // 6250 (final)
    const int nblkc = NN / NPC;                      // 3125 (input/combine)

    // CSR build (per launch; graph-captured)
    cudaMemsetAsync(degp, 0, NN * sizeof(int));
    count_kernel<<<(NE + 255) / 256, 256>>>(dst);
    scan_kernel<<<1, SCAN_T>>>();
    fill_kernel<<<(NE + 255) / 256, 256>>>(src, dst);

    input_kernel<<<nblkc, 128>>>(x, in_g, in_b, inW, inPb, buf[0]);

    for (int l = 0; l < NL; l++) {
        combine_kernel<<<nblkc, 128>>>(buf[l & 1], buf[(l + 1) & 1],
                                       Wl + (size_t)l * HID * HID,
                                       bl + l * HID,
                                       Wr + (size_t)l * HID * HID,
                                       ng + l * HID,
                                       nbta + l * HID);
    }

    final_kernel<<<nblk, 128>>>(buf[NL & 1], og, ob, oW, oPb, out);
}